// round 1
// baseline (speedup 1.0000x reference)
#include <cuda_runtime.h>
#include <math.h>

#define B      8192
#define IN_DIM 1024
#define HID    512
#define OUT    128

// scratch (device globals — no allocation allowed)
__device__ float g_h[B * HID];     // 16 MB
__device__ float g_zn[B * OUT];    // 4 MB

// ---------------------------------------------------------------------------
// Kernel 1: h = PReLU(x @ w1 + b1)
// tile 64x64, BK=16, 256 threads, 4x4 microtile
// ---------------------------------------------------------------------------
__global__ __launch_bounds__(256) void gemm1_kernel(
    const float* __restrict__ x, const float* __restrict__ w1,
    const float* __restrict__ b1, const float* __restrict__ prelu_a)
{
    __shared__ float As[16][68];   // As[k][m]
    __shared__ float Bs[16][68];   // Bs[k][n]

    const int tid = threadIdx.x;
    const int tx = tid & 15;       // col group
    const int ty = tid >> 4;       // row group
    const int rb = blockIdx.y;     // row block (0..127)
    const int cb = blockIdx.x;     // col block (0..7)

    float acc[4][4] = {};

    const int a_m  = tid >> 2;           // 0..63
    const int a_k4 = (tid & 3) * 4;      // 0,4,8,12
    const int b_k  = tid >> 4;           // 0..15
    const int b_n4 = (tid & 15) * 4;     // 0..60

    const float* xg = x  + (rb * 64 + a_m) * IN_DIM + a_k4;
    const float* wg = w1 + b_k * HID + cb * 64 + b_n4;

    for (int kt = 0; kt < IN_DIM / 16; ++kt) {
        float4 av = *(const float4*)(xg + kt * 16);
        As[a_k4 + 0][a_m] = av.x;
        As[a_k4 + 1][a_m] = av.y;
        As[a_k4 + 2][a_m] = av.z;
        As[a_k4 + 3][a_m] = av.w;
        float4 bv = *(const float4*)(wg + kt * 16 * HID);
        *(float4*)&Bs[b_k][b_n4] = bv;
        __syncthreads();
#pragma unroll
        for (int k = 0; k < 16; ++k) {
            float a[4], bb[4];
#pragma unroll
            for (int i = 0; i < 4; ++i) a[i]  = As[k][ty * 4 + i];
#pragma unroll
            for (int j = 0; j < 4; ++j) bb[j] = Bs[k][tx * 4 + j];
#pragma unroll
            for (int i = 0; i < 4; ++i)
#pragma unroll
                for (int j = 0; j < 4; ++j)
                    acc[i][j] = fmaf(a[i], bb[j], acc[i][j]);
        }
        __syncthreads();
    }

    const float alpha = prelu_a[0];
#pragma unroll
    for (int i = 0; i < 4; ++i) {
        const int r = rb * 64 + ty * 4 + i;
#pragma unroll
        for (int j = 0; j < 4; ++j) {
            const int c = cb * 64 + tx * 4 + j;
            float v = acc[i][j] + b1[c];
            v = (v >= 0.0f) ? v : alpha * v;
            g_h[r * HID + c] = v;
        }
    }
}

// ---------------------------------------------------------------------------
// Kernel 2: in-place LayerNorm over rows of g_h (HID=512), 128 threads/row
// ---------------------------------------------------------------------------
__global__ __launch_bounds__(128) void ln_kernel(
    const float* __restrict__ gamma, const float* __restrict__ beta)
{
    const int row = blockIdx.x;
    float* hp = g_h + row * HID;
    const int tid = threadIdx.x;

    float v[4];
    float s = 0.f, ss = 0.f;
#pragma unroll
    for (int i = 0; i < 4; ++i) {
        v[i] = hp[tid + i * 128];
        s  += v[i];
        ss += v[i] * v[i];
    }
#pragma unroll
    for (int o = 16; o > 0; o >>= 1) {
        s  += __shfl_xor_sync(0xFFFFFFFFu, s,  o);
        ss += __shfl_xor_sync(0xFFFFFFFFu, ss, o);
    }
    __shared__ float sm[4], sm2[4];
    if ((tid & 31) == 0) { sm[tid >> 5] = s; sm2[tid >> 5] = ss; }
    __syncthreads();
    s  = sm[0]  + sm[1]  + sm[2]  + sm[3];
    ss = sm2[0] + sm2[1] + sm2[2] + sm2[3];

    const float mu   = s * (1.0f / HID);
    const float var  = ss * (1.0f / HID) - mu * mu;
    const float rstd = rsqrtf(var + 1e-6f);
#pragma unroll
    for (int i = 0; i < 4; ++i) {
        const int c = tid + i * 128;
        hp[c] = (v[i] - mu) * rstd * gamma[c] + beta[c];
    }
}

// ---------------------------------------------------------------------------
// Kernel 3: z = hn @ w2 + b2 (to d_out), zn = z / max(||z||,eps) (to g_zn)
// tile 64x128, BK=32, 256 threads, 4x8 microtile (full OUT width per block)
// ---------------------------------------------------------------------------
__global__ __launch_bounds__(256) void gemm2_kernel(
    const float* __restrict__ w2, const float* __restrict__ b2,
    float* __restrict__ z_out)
{
    __shared__ float As[32][68];    // As[k][m]
    __shared__ float Bs[32][132];   // Bs[k][n]
    __shared__ float rowsq[64];

    const int tid = threadIdx.x;
    const int tx = tid & 15;        // col group (8 cols each)
    const int ty = tid >> 4;        // row group (4 rows each)
    const int rb = blockIdx.x;      // row block 0..127

    float acc[4][8] = {};

    for (int kt = 0; kt < HID / 32; ++kt) {
        // load A: 64 rows x 32 k = 512 float4
#pragma unroll
        for (int l = 0; l < 2; ++l) {
            const int idx = tid + l * 256;
            const int m  = idx >> 3;
            const int k4 = (idx & 7) * 4;
            float4 av = *(const float4*)&g_h[(rb * 64 + m) * HID + kt * 32 + k4];
            As[k4 + 0][m] = av.x;
            As[k4 + 1][m] = av.y;
            As[k4 + 2][m] = av.z;
            As[k4 + 3][m] = av.w;
        }
        // load B: 32 k x 128 n = 1024 float4
#pragma unroll
        for (int l = 0; l < 4; ++l) {
            const int idx = tid + l * 256;
            const int k  = idx >> 5;
            const int n4 = (idx & 31) * 4;
            float4 bv = *(const float4*)&w2[(kt * 32 + k) * OUT + n4];
            *(float4*)&Bs[k][n4] = bv;
        }
        __syncthreads();
#pragma unroll
        for (int k = 0; k < 32; ++k) {
            float a[4], bb[8];
#pragma unroll
            for (int i = 0; i < 4; ++i) a[i]  = As[k][ty * 4 + i];
#pragma unroll
            for (int j = 0; j < 8; ++j) bb[j] = Bs[k][tx * 8 + j];
#pragma unroll
            for (int i = 0; i < 4; ++i)
#pragma unroll
                for (int j = 0; j < 8; ++j)
                    acc[i][j] = fmaf(a[i], bb[j], acc[i][j]);
        }
        __syncthreads();
    }

    // epilogue: bias, row sum-of-squares, write z + zn
    for (int i = tid; i < 64; i += 256) rowsq[i] = 0.f;
    __syncthreads();

    float partial[4] = {};
#pragma unroll
    for (int i = 0; i < 4; ++i)
#pragma unroll
        for (int j = 0; j < 8; ++j) {
            const int c = tx * 8 + j;
            acc[i][j] += b2[c];
            partial[i] += acc[i][j] * acc[i][j];
        }
#pragma unroll
    for (int i = 0; i < 4; ++i) atomicAdd(&rowsq[ty * 4 + i], partial[i]);
    __syncthreads();

#pragma unroll
    for (int i = 0; i < 4; ++i) {
        const int r = rb * 64 + ty * 4 + i;
        const float inv = 1.0f / fmaxf(sqrtf(rowsq[ty * 4 + i]), 1e-8f);
#pragma unroll
        for (int j = 0; j < 8; ++j) {
            const int c = tx * 8 + j;
            z_out[r * OUT + c] = acc[i][j];
            g_zn[r * OUT + c] = acc[i][j] * inv;
        }
    }
}

// ---------------------------------------------------------------------------
// Kernel 4: y_hat = zn @ zn^T, symmetric — compute only bj >= bi, mirror via
// SMEM transpose so both tiles are written coalesced.
// tile 64x64, K=128 in two 64-chunks, 256 threads, 4x4 microtile
// ---------------------------------------------------------------------------
__global__ __launch_bounds__(256) void gram_kernel(float* __restrict__ yhat)
{
    const int bi = blockIdx.y;
    const int bj = blockIdx.x;
    if (bj < bi) return;

    __shared__ float As[64][68];   // As[k][m]
    __shared__ float Bs[64][68];   // Bs[k][n]

    const int tid = threadIdx.x;
    const int tx = tid & 15;
    const int ty = tid >> 4;

    float acc[4][4] = {};

#pragma unroll
    for (int kc = 0; kc < 2; ++kc) {
        // each chunk: 64 rows x 64 k = 1024 float4 per tile
#pragma unroll
        for (int l = 0; l < 4; ++l) {
            const int idx = tid + l * 256;
            const int m  = idx >> 4;
            const int k4 = (idx & 15) * 4;
            float4 av = *(const float4*)&g_zn[(bi * 64 + m) * OUT + kc * 64 + k4];
            As[k4 + 0][m] = av.x;
            As[k4 + 1][m] = av.y;
            As[k4 + 2][m] = av.z;
            As[k4 + 3][m] = av.w;
            float4 bv = *(const float4*)&g_zn[(bj * 64 + m) * OUT + kc * 64 + k4];
            Bs[k4 + 0][m] = bv.x;
            Bs[k4 + 1][m] = bv.y;
            Bs[k4 + 2][m] = bv.z;
            Bs[k4 + 3][m] = bv.w;
        }
        __syncthreads();
#pragma unroll 16
        for (int k = 0; k < 64; ++k) {
            float a[4], bb[4];
#pragma unroll
            for (int i = 0; i < 4; ++i) a[i]  = As[k][ty * 4 + i];
#pragma unroll
            for (int j = 0; j < 4; ++j) bb[j] = Bs[k][tx * 4 + j];
#pragma unroll
            for (int i = 0; i < 4; ++i)
#pragma unroll
                for (int j = 0; j < 4; ++j)
                    acc[i][j] = fmaf(a[i], bb[j], acc[i][j]);
        }
        __syncthreads();
    }

    // direct tile [bi, bj] — coalesced
#pragma unroll
    for (int i = 0; i < 4; ++i) {
        const long r = bi * 64 + ty * 4 + i;
#pragma unroll
        for (int j = 0; j < 4; ++j) {
            const long c = bj * 64 + tx * 4 + j;
            yhat[r * (long)B + c] = acc[i][j];
        }
    }

    if (bi != bj) {
        // mirror tile [bj, bi] via SMEM transpose (reuse As storage)
        float (*Cs)[65] = (float(*)[65])As;   // 64*65 = 4160 <= 64*68 floats
#pragma unroll
        for (int i = 0; i < 4; ++i)
#pragma unroll
            for (int j = 0; j < 4; ++j)
                Cs[ty * 4 + i][tx * 4 + j] = acc[i][j];
        __syncthreads();
#pragma unroll
        for (int l = 0; l < 16; ++l) {
            const int idx = tid + l * 256;
            const int r = idx >> 6;   // row within mirrored tile = original col
            const int c = idx & 63;   // col within mirrored tile = original row
            yhat[(long)(bj * 64 + r) * (long)B + (bi * 64 + c)] = Cs[c][r];
        }
    }
}

// ---------------------------------------------------------------------------
extern "C" void kernel_launch(void* const* d_in, const int* in_sizes, int n_in,
                              void* d_out, int out_size)
{
    const float* x       = (const float*)d_in[0];
    const float* w1      = (const float*)d_in[1];
    const float* b1      = (const float*)d_in[2];
    const float* prelu_a = (const float*)d_in[3];
    const float* gamma   = (const float*)d_in[4];
    const float* beta    = (const float*)d_in[5];
    const float* w2      = (const float*)d_in[6];
    const float* b2      = (const float*)d_in[7];

    float* out   = (float*)d_out;
    float* z_out = out;                    // [8192, 128]
    float* yhat  = out + (size_t)B * OUT;  // [8192, 8192]

    gemm1_kernel<<<dim3(HID / 64, B / 64), 256>>>(x, w1, b1, prelu_a);
    ln_kernel<<<B, 128>>>(gamma, beta);
    gemm2_kernel<<<B / 64, 256>>>(w2, b2, z_out);
    gram_kernel<<<dim3(B / 64, B / 64), 256>>>(yhat);
}

// round 4
// speedup vs baseline: 1.4406x; 1.4406x over previous
#include <cuda_runtime.h>
#include <cuda_bf16.h>
#include <math.h>
#include <cstdint>

#define B      8192
#define IN_DIM 1024
#define HID    512
#define OUT    128

// scratch (device globals — no allocation allowed)
__device__ float g_h[B * HID];                 // 16 MB
__device__ __nv_bfloat16 g_zn_hi[B * OUT];     // 2 MB
__device__ __nv_bfloat16 g_zn_lo[B * OUT];     // 2 MB

__device__ __forceinline__ uint32_t smem_u32(const void* p) {
    uint32_t a;
    asm("{ .reg .u64 t; cvta.to.shared.u64 t, %1; cvt.u32.u64 %0, t; }"
        : "=r"(a) : "l"(p));
    return a;
}

#define LDSM_X4(r0, r1, r2, r3, addr) \
    asm volatile("ldmatrix.sync.aligned.m8n8.x4.shared.b16 {%0,%1,%2,%3}, [%4];" \
        : "=r"(r0), "=r"(r1), "=r"(r2), "=r"(r3) : "r"(addr))

#define MMA_BF16(d, a, b0, b1) \
    asm volatile("mma.sync.aligned.m16n8k16.row.col.f32.bf16.bf16.f32 " \
        "{%0,%1,%2,%3}, {%4,%5,%6,%7}, {%8,%9}, {%0,%1,%2,%3};" \
        : "+f"((d)[0]), "+f"((d)[1]), "+f"((d)[2]), "+f"((d)[3]) \
        : "r"((a)[0]), "r"((a)[1]), "r"((a)[2]), "r"((a)[3]), "r"(b0), "r"(b1))

// ---------------------------------------------------------------------------
// Kernel 1: h = PReLU(x @ w1 + b1)   (fp32, 64x64x16, 4x4 microtile)
// ---------------------------------------------------------------------------
__global__ __launch_bounds__(256) void gemm1_kernel(
    const float* __restrict__ x, const float* __restrict__ w1,
    const float* __restrict__ b1, const float* __restrict__ prelu_a)
{
    __shared__ float As[16][68];
    __shared__ float Bs[16][68];

    const int tid = threadIdx.x;
    const int tx = tid & 15;
    const int ty = tid >> 4;
    const int rb = blockIdx.y;
    const int cb = blockIdx.x;

    float acc[4][4] = {};

    const int a_m  = tid >> 2;
    const int a_k4 = (tid & 3) * 4;
    const int b_k  = tid >> 4;
    const int b_n4 = (tid & 15) * 4;

    const float* xg = x  + (rb * 64 + a_m) * IN_DIM + a_k4;
    const float* wg = w1 + b_k * HID + cb * 64 + b_n4;

    for (int kt = 0; kt < IN_DIM / 16; ++kt) {
        float4 av = *(const float4*)(xg + kt * 16);
        As[a_k4 + 0][a_m] = av.x;
        As[a_k4 + 1][a_m] = av.y;
        As[a_k4 + 2][a_m] = av.z;
        As[a_k4 + 3][a_m] = av.w;
        float4 bv = *(const float4*)(wg + kt * 16 * HID);
        *(float4*)&Bs[b_k][b_n4] = bv;
        __syncthreads();
#pragma unroll
        for (int k = 0; k < 16; ++k) {
            float a[4], bb[4];
#pragma unroll
            for (int i = 0; i < 4; ++i) a[i]  = As[k][ty * 4 + i];
#pragma unroll
            for (int j = 0; j < 4; ++j) bb[j] = Bs[k][tx * 4 + j];
#pragma unroll
            for (int i = 0; i < 4; ++i)
#pragma unroll
                for (int j = 0; j < 4; ++j)
                    acc[i][j] = fmaf(a[i], bb[j], acc[i][j]);
        }
        __syncthreads();
    }

    const float alpha = prelu_a[0];
#pragma unroll
    for (int i = 0; i < 4; ++i) {
        const int r = rb * 64 + ty * 4 + i;
#pragma unroll
        for (int j = 0; j < 4; ++j) {
            const int c = cb * 64 + tx * 4 + j;
            float v = acc[i][j] + b1[c];
            v = (v >= 0.0f) ? v : alpha * v;
            g_h[r * HID + c] = v;
        }
    }
}

// ---------------------------------------------------------------------------
// Kernel 2: in-place LayerNorm over rows of g_h
// ---------------------------------------------------------------------------
__global__ __launch_bounds__(128) void ln_kernel(
    const float* __restrict__ gamma, const float* __restrict__ beta)
{
    const int row = blockIdx.x;
    float* hp = g_h + row * HID;
    const int tid = threadIdx.x;

    float v[4];
    float s = 0.f, ss = 0.f;
#pragma unroll
    for (int i = 0; i < 4; ++i) {
        v[i] = hp[tid + i * 128];
        s  += v[i];
        ss += v[i] * v[i];
    }
#pragma unroll
    for (int o = 16; o > 0; o >>= 1) {
        s  += __shfl_xor_sync(0xFFFFFFFFu, s,  o);
        ss += __shfl_xor_sync(0xFFFFFFFFu, ss, o);
    }
    __shared__ float sm[4], sm2[4];
    if ((tid & 31) == 0) { sm[tid >> 5] = s; sm2[tid >> 5] = ss; }
    __syncthreads();
    s  = sm[0]  + sm[1]  + sm[2]  + sm[3];
    ss = sm2[0] + sm2[1] + sm2[2] + sm2[3];

    const float mu   = s * (1.0f / HID);
    const float var  = ss * (1.0f / HID) - mu * mu;
    const float rstd = rsqrtf(var + 1e-6f);
#pragma unroll
    for (int i = 0; i < 4; ++i) {
        const int c = tid + i * 128;
        hp[c] = (v[i] - mu) * rstd * gamma[c] + beta[c];
    }
}

// ---------------------------------------------------------------------------
// Kernel 3: z = hn @ w2 + b2 -> d_out; zn split into bf16 hi/lo for the gram
// ---------------------------------------------------------------------------
__global__ __launch_bounds__(256) void gemm2_kernel(
    const float* __restrict__ w2, const float* __restrict__ b2,
    float* __restrict__ z_out)
{
    __shared__ float As[32][68];
    __shared__ float Bs[32][132];
    __shared__ float rowsq[64];

    const int tid = threadIdx.x;
    const int tx = tid & 15;
    const int ty = tid >> 4;
    const int rb = blockIdx.x;

    float acc[4][8] = {};

    for (int kt = 0; kt < HID / 32; ++kt) {
#pragma unroll
        for (int l = 0; l < 2; ++l) {
            const int idx = tid + l * 256;
            const int m  = idx >> 3;
            const int k4 = (idx & 7) * 4;
            float4 av = *(const float4*)&g_h[(rb * 64 + m) * HID + kt * 32 + k4];
            As[k4 + 0][m] = av.x;
            As[k4 + 1][m] = av.y;
            As[k4 + 2][m] = av.z;
            As[k4 + 3][m] = av.w;
        }
#pragma unroll
        for (int l = 0; l < 4; ++l) {
            const int idx = tid + l * 256;
            const int k  = idx >> 5;
            const int n4 = (idx & 31) * 4;
            float4 bv = *(const float4*)&w2[(kt * 32 + k) * OUT + n4];
            *(float4*)&Bs[k][n4] = bv;
        }
        __syncthreads();
#pragma unroll
        for (int k = 0; k < 32; ++k) {
            float a[4], bb[8];
#pragma unroll
            for (int i = 0; i < 4; ++i) a[i]  = As[k][ty * 4 + i];
#pragma unroll
            for (int j = 0; j < 8; ++j) bb[j] = Bs[k][tx * 8 + j];
#pragma unroll
            for (int i = 0; i < 4; ++i)
#pragma unroll
                for (int j = 0; j < 8; ++j)
                    acc[i][j] = fmaf(a[i], bb[j], acc[i][j]);
        }
        __syncthreads();
    }

    for (int i = tid; i < 64; i += 256) rowsq[i] = 0.f;
    __syncthreads();

    float partial[4] = {};
#pragma unroll
    for (int i = 0; i < 4; ++i)
#pragma unroll
        for (int j = 0; j < 8; ++j) {
            const int c = tx * 8 + j;
            acc[i][j] += b2[c];
            partial[i] += acc[i][j] * acc[i][j];
        }
#pragma unroll
    for (int i = 0; i < 4; ++i) atomicAdd(&rowsq[ty * 4 + i], partial[i]);
    __syncthreads();

#pragma unroll
    for (int i = 0; i < 4; ++i) {
        const int r = rb * 64 + ty * 4 + i;
        const float inv = 1.0f / fmaxf(sqrtf(rowsq[ty * 4 + i]), 1e-8f);
#pragma unroll
        for (int j = 0; j < 8; ++j) {
            const int c = tx * 8 + j;
            z_out[r * OUT + c] = acc[i][j];
            const float zn = acc[i][j] * inv;
            __nv_bfloat16 hi = __float2bfloat16(zn);
            __nv_bfloat16 lo = __float2bfloat16(zn - __bfloat162float(hi));
            g_zn_hi[r * OUT + c] = hi;
            g_zn_lo[r * OUT + c] = lo;
        }
    }
}

// ---------------------------------------------------------------------------
// Kernel 4: y_hat = zn @ zn^T via mma.sync bf16 split (hi*hi + hi*lo + lo*hi)
// 128x128 tile/CTA, 8 warps (4 in M x 2 in N), warp tile 32x64.
// Triangular grid, SMEM-staged symmetric mirror.
// ---------------------------------------------------------------------------
#define ROWB   272                      // smem row stride bytes (K=128 bf16 = 256B + 16B pad)
#define TILEB  (128 * ROWB)             // 34816 B per operand tile
#define GRAM_SMEM (4 * TILEB)           // 139264 B; C-staging (128*133*4=68KB) reuses it

__global__ __launch_bounds__(256, 1) void gram_mma_kernel(float* __restrict__ yhat)
{
    const int bi = blockIdx.y;
    const int bj = blockIdx.x;
    if (bj < bi) return;

    extern __shared__ char smem[];
    const uint32_t sb = smem_u32(smem);
    const int tid = threadIdx.x;
    const int wid = tid >> 5;
    const int lane = tid & 31;
    const int wm = wid & 3;       // warp row (32 rows)
    const int wn = wid >> 2;      // warp col (64 cols)

    // ---- load 4 operand tiles: A_hi, A_lo, B_hi, B_lo (row-major, 272B stride)
    // 128 rows x 256 B = 2048 16B-chunks per tile (16 chunks/row)
#pragma unroll
    for (int op = 0; op < 4; ++op) {
        const __nv_bfloat16* g = (op & 1) ? g_zn_lo : g_zn_hi;
        const int rowbase = ((op < 2) ? bi : bj) * 128;
        char* dst = smem + op * TILEB;
#pragma unroll
        for (int it = 0; it < 8; ++it) {
            const int idx = tid + it * 256;      // 0..2047 16B-chunks
            const int row = idx >> 4;            // 0..127
            const int c16 = idx & 15;            // 16B chunk within 256B row
            const float4 v = *(const float4*)(g + (rowbase + row) * OUT + c16 * 8);
            *(float4*)(dst + row * ROWB + c16 * 16) = v;
        }
    }
    __syncthreads();

    float acc[2][8][4] = {};

    const uint32_t lrow  = (uint32_t)(lane & 15);
    const uint32_t lcol  = (uint32_t)(lane >> 4) * 16;
    const uint32_t aoff  = (uint32_t)(wm * 32) * ROWB + lrow * ROWB + lcol;
    const uint32_t boff  = (uint32_t)(wn * 64) * ROWB + lrow * ROWB + lcol;

    // splits: s=0: hi*hi, s=1: hi*lo, s=2: lo*hi
#pragma unroll
    for (int s = 0; s < 3; ++s) {
        const uint32_t aBase = sb + ((s == 2) ? 1 : 0) * TILEB + aoff;
        const uint32_t bBase = sb + ((s == 1) ? 3 : 2) * TILEB + boff;
#pragma unroll
        for (int ks = 0; ks < 8; ++ks) {
            const uint32_t kb = (uint32_t)ks * 32;
            uint32_t a[2][4];
            LDSM_X4(a[0][0], a[0][1], a[0][2], a[0][3], aBase + kb);
            LDSM_X4(a[1][0], a[1][1], a[1][2], a[1][3], aBase + 16 * ROWB + kb);
            uint32_t b[8][2];
#pragma unroll
            for (int p = 0; p < 4; ++p) {
                uint32_t r0, r1, r2, r3;
                LDSM_X4(r0, r1, r2, r3, bBase + (uint32_t)p * 16 * ROWB + kb);
                b[2 * p + 0][0] = r0; b[2 * p + 0][1] = r2;
                b[2 * p + 1][0] = r1; b[2 * p + 1][1] = r3;
            }
#pragma unroll
            for (int i = 0; i < 2; ++i)
#pragma unroll
                for (int j = 0; j < 8; ++j)
                    MMA_BF16(acc[i][j], a[i], b[j][0], b[j][1]);
        }
    }

    __syncthreads();   // operand tiles dead; reuse smem for C staging

    // ---- stage C into smem, stride 133 floats (conflict-free transpose)
    float* Cs = (float*)smem;
#pragma unroll
    for (int i = 0; i < 2; ++i) {
        const int r0 = wm * 32 + i * 16 + (lane >> 2);
#pragma unroll
        for (int j = 0; j < 8; ++j) {
            const int c0 = wn * 64 + j * 8 + (lane & 3) * 2;
            Cs[r0 * 133 + c0]       = acc[i][j][0];
            Cs[r0 * 133 + c0 + 1]   = acc[i][j][1];
            Cs[(r0 + 8) * 133 + c0]     = acc[i][j][2];
            Cs[(r0 + 8) * 133 + c0 + 1] = acc[i][j][3];
        }
    }
    __syncthreads();

    // ---- coalesced writes: direct tile + mirrored tile
    const long rowD = (long)bi * 128;
    const long colD = (long)bj * 128;
#pragma unroll
    for (int it = 0; it < 64; ++it) {
        const int idx = tid + it * 256;
        const int r = idx >> 7;
        const int c = idx & 127;
        yhat[(rowD + r) * (long)B + colD + c] = Cs[r * 133 + c];
    }
    if (bi != bj) {
#pragma unroll
        for (int it = 0; it < 64; ++it) {
            const int idx = tid + it * 256;
            const int r = idx >> 7;
            const int c = idx & 127;
            yhat[((long)bj * 128 + r) * (long)B + (long)bi * 128 + c] = Cs[c * 133 + r];
        }
    }
}

// ---------------------------------------------------------------------------
extern "C" void kernel_launch(void* const* d_in, const int* in_sizes, int n_in,
                              void* d_out, int out_size)
{
    const float* x       = (const float*)d_in[0];
    const float* w1      = (const float*)d_in[1];
    const float* b1      = (const float*)d_in[2];
    const float* prelu_a = (const float*)d_in[3];
    const float* gamma   = (const float*)d_in[4];
    const float* beta    = (const float*)d_in[5];
    const float* w2      = (const float*)d_in[6];
    const float* b2      = (const float*)d_in[7];

    float* out   = (float*)d_out;
    float* z_out = out;                    // [8192, 128]
    float* yhat  = out + (size_t)B * OUT;  // [8192, 8192]

    cudaFuncSetAttribute(gram_mma_kernel,
                         cudaFuncAttributeMaxDynamicSharedMemorySize,
                         GRAM_SMEM);

    gemm1_kernel<<<dim3(HID / 64, B / 64), 256>>>(x, w1, b1, prelu_a);
    ln_kernel<<<B, 128>>>(gamma, beta);
    gemm2_kernel<<<B / 64, 256>>>(w2, b2, z_out);
    gram_mma_kernel<<<dim3(B / 128, B / 128), 256, GRAM_SMEM>>>(yhat);
}

// round 5
// speedup vs baseline: 1.8019x; 1.2508x over previous
#include <cuda_runtime.h>
#include <cuda_bf16.h>
#include <math.h>
#include <cstdint>

#define B      8192
#define IN_DIM 1024
#define HID    512
#define OUT    128

// scratch (device globals — no allocation allowed)
__device__ float g_h[B * HID];                  // 16 MB (gemm1 out, pre-LN)
__device__ __nv_bfloat16 g_x_hi[B * IN_DIM];    // 16 MB
__device__ __nv_bfloat16 g_x_lo[B * IN_DIM];    // 16 MB
__device__ __nv_bfloat16 g_w1t_hi[HID * IN_DIM];  // 1 MB  [n][k]
__device__ __nv_bfloat16 g_w1t_lo[HID * IN_DIM];  // 1 MB
__device__ __nv_bfloat16 g_hn_hi[B * HID];      // 8 MB (post-LN)
__device__ __nv_bfloat16 g_hn_lo[B * HID];      // 8 MB
__device__ __nv_bfloat16 g_w2t_hi[OUT * HID];   // 128 KB [n][k]
__device__ __nv_bfloat16 g_w2t_lo[OUT * HID];   // 128 KB
__device__ __nv_bfloat16 g_zn_hi[B * OUT];      // 2 MB
__device__ __nv_bfloat16 g_zn_lo[B * OUT];      // 2 MB

__device__ __forceinline__ uint32_t smem_u32(const void* p) {
    uint32_t a;
    asm("{ .reg .u64 t; cvta.to.shared.u64 t, %1; cvt.u32.u64 %0, t; }"
        : "=r"(a) : "l"(p));
    return a;
}

#define LDSM_X4(r0, r1, r2, r3, addr) \
    asm volatile("ldmatrix.sync.aligned.m8n8.x4.shared.b16 {%0,%1,%2,%3}, [%4];" \
        : "=r"(r0), "=r"(r1), "=r"(r2), "=r"(r3) : "r"(addr))

#define MMA_BF16(d, a, b0, b1) \
    asm volatile("mma.sync.aligned.m16n8k16.row.col.f32.bf16.bf16.f32 " \
        "{%0,%1,%2,%3}, {%4,%5,%6,%7}, {%8,%9}, {%0,%1,%2,%3};" \
        : "+f"((d)[0]), "+f"((d)[1]), "+f"((d)[2]), "+f"((d)[3]) \
        : "r"((a)[0]), "r"((a)[1]), "r"((a)[2]), "r"((a)[3]), "r"(b0), "r"(b1))

#define ROWB   272                      // smem row stride (256B data + 16B pad)
#define TILEB  (128 * ROWB)             // 34816 B per operand tile
#define MMA_SMEM (4 * TILEB)            // 139264 B

// load a 128x128-bf16 tile (g pre-offset to tile origin; gstride in elems)
__device__ __forceinline__ void load_tile(
    const __nv_bfloat16* __restrict__ g, int gstride, char* dst, int tid)
{
#pragma unroll
    for (int it = 0; it < 8; ++it) {
        const int idx = tid + it * 256;
        const int row = idx >> 4;
        const int c16 = idx & 15;
        const float4 v = *(const float4*)(g + row * gstride + c16 * 8);
        *(float4*)(dst + row * ROWB + c16 * 16) = v;
    }
}

// 3-split mma over one k=128 chunk: (Ah,Bh) + (Ah,Bl) + (Al,Bh)
__device__ __forceinline__ void mma_3split(
    uint32_t aH, uint32_t aL, uint32_t bH, uint32_t bL, float acc[2][8][4])
{
#pragma unroll
    for (int s = 0; s < 3; ++s) {
        const uint32_t aBase = (s == 2) ? aL : aH;
        const uint32_t bBase = (s == 1) ? bL : bH;
#pragma unroll
        for (int ks = 0; ks < 8; ++ks) {
            const uint32_t kb = (uint32_t)ks * 32;
            uint32_t a[2][4];
            LDSM_X4(a[0][0], a[0][1], a[0][2], a[0][3], aBase + kb);
            LDSM_X4(a[1][0], a[1][1], a[1][2], a[1][3], aBase + 16 * ROWB + kb);
            uint32_t b[8][2];
#pragma unroll
            for (int p = 0; p < 4; ++p) {
                uint32_t r0, r1, r2, r3;
                LDSM_X4(r0, r1, r2, r3, bBase + (uint32_t)p * 16 * ROWB + kb);
                b[2 * p + 0][0] = r0; b[2 * p + 0][1] = r2;
                b[2 * p + 1][0] = r1; b[2 * p + 1][1] = r3;
            }
#pragma unroll
            for (int i = 0; i < 2; ++i)
#pragma unroll
                for (int j = 0; j < 8; ++j)
                    MMA_BF16(acc[i][j], a[i], b[j][0], b[j][1]);
        }
    }
}

// stage acc fragments into Cs (stride 133 floats)
__device__ __forceinline__ void stage_acc(
    float* Cs, const float acc[2][8][4], int wm, int wn, int lane)
{
#pragma unroll
    for (int i = 0; i < 2; ++i) {
        const int r0 = wm * 32 + i * 16 + (lane >> 2);
#pragma unroll
        for (int j = 0; j < 8; ++j) {
            const int c0 = wn * 64 + j * 8 + (lane & 3) * 2;
            Cs[r0 * 133 + c0]           = acc[i][j][0];
            Cs[r0 * 133 + c0 + 1]       = acc[i][j][1];
            Cs[(r0 + 8) * 133 + c0]     = acc[i][j][2];
            Cs[(r0 + 8) * 133 + c0 + 1] = acc[i][j][3];
        }
    }
}

// ---------------------------------------------------------------------------
// Prologue kernels: split/transpose inputs to bf16 hi/lo
// ---------------------------------------------------------------------------
__global__ __launch_bounds__(256) void split_x_kernel(const float* __restrict__ x)
{
    const int idx = blockIdx.x * 256 + threadIdx.x;      // 4M threads, 2 elems each
    const float2 v = ((const float2*)x)[idx];
    const __nv_bfloat16 h0 = __float2bfloat16(v.x);
    const __nv_bfloat16 h1 = __float2bfloat16(v.y);
    g_x_hi[2 * idx]     = h0;
    g_x_hi[2 * idx + 1] = h1;
    g_x_lo[2 * idx]     = __float2bfloat16(v.x - __bfloat162float(h0));
    g_x_lo[2 * idx + 1] = __float2bfloat16(v.y - __bfloat162float(h1));
}

__global__ __launch_bounds__(256) void split_w1t_kernel(const float* __restrict__ w1)
{
    const int idx = blockIdx.x * 256 + threadIdx.x;      // 512K
    const int n = idx >> 10, k = idx & 1023;
    const float v = w1[k * HID + n];
    const __nv_bfloat16 h = __float2bfloat16(v);
    g_w1t_hi[idx] = h;
    g_w1t_lo[idx] = __float2bfloat16(v - __bfloat162float(h));
}

__global__ __launch_bounds__(256) void split_w2t_kernel(const float* __restrict__ w2)
{
    const int idx = blockIdx.x * 256 + threadIdx.x;      // 64K
    const int n = idx >> 9, k = idx & 511;
    const float v = w2[k * OUT + n];
    const __nv_bfloat16 h = __float2bfloat16(v);
    g_w2t_hi[idx] = h;
    g_w2t_lo[idx] = __float2bfloat16(v - __bfloat162float(h));
}

// ---------------------------------------------------------------------------
// Kernel 1: h = PReLU(x @ w1 + b1) via split-bf16 HMMA. tile 128x128, K=1024.
// ---------------------------------------------------------------------------
__global__ __launch_bounds__(256, 1) void gemm1_mma_kernel(
    const float* __restrict__ b1, const float* __restrict__ prelu_a)
{
    extern __shared__ char smem[];
    const uint32_t sb = smem_u32(smem);
    const int tid = threadIdx.x;
    const int wid = tid >> 5;
    const int lane = tid & 31;
    const int wm = wid & 3, wn = wid >> 2;
    const int rb = blockIdx.y, cb = blockIdx.x;

    const uint32_t lrow = (uint32_t)(lane & 15);
    const uint32_t lcol = (uint32_t)(lane >> 4) * 16;
    const uint32_t aoff = (uint32_t)(wm * 32) * ROWB + lrow * ROWB + lcol;
    const uint32_t boff = (uint32_t)(wn * 64) * ROWB + lrow * ROWB + lcol;

    float acc[2][8][4] = {};

    for (int kt = 0; kt < IN_DIM / 128; ++kt) {
        const int k0 = kt * 128;
        load_tile(g_x_hi   + (rb * 128) * IN_DIM + k0, IN_DIM, smem + 0 * TILEB, tid);
        load_tile(g_x_lo   + (rb * 128) * IN_DIM + k0, IN_DIM, smem + 1 * TILEB, tid);
        load_tile(g_w1t_hi + (cb * 128) * IN_DIM + k0, IN_DIM, smem + 2 * TILEB, tid);
        load_tile(g_w1t_lo + (cb * 128) * IN_DIM + k0, IN_DIM, smem + 3 * TILEB, tid);
        __syncthreads();
        mma_3split(sb + 0 * TILEB + aoff, sb + 1 * TILEB + aoff,
                   sb + 2 * TILEB + boff, sb + 3 * TILEB + boff, acc);
        __syncthreads();
    }

    float* Cs = (float*)smem;
    stage_acc(Cs, acc, wm, wn, lane);
    __syncthreads();

    const float alpha = prelu_a[0];
#pragma unroll
    for (int it = 0; it < 64; ++it) {
        const int idx = tid + it * 256;
        const int r = idx >> 7, c = idx & 127;
        float v = Cs[r * 133 + c] + b1[cb * 128 + c];
        v = (v >= 0.0f) ? v : alpha * v;
        g_h[(rb * 128 + r) * HID + cb * 128 + c] = v;
    }
}

// ---------------------------------------------------------------------------
// Kernel 2: LayerNorm rows of g_h -> hn split bf16 hi/lo
// ---------------------------------------------------------------------------
__global__ __launch_bounds__(128) void ln_split_kernel(
    const float* __restrict__ gamma, const float* __restrict__ beta)
{
    const int row = blockIdx.x;
    const float* hp = g_h + row * HID;
    const int tid = threadIdx.x;

    float v[4];
    float s = 0.f, ss = 0.f;
#pragma unroll
    for (int i = 0; i < 4; ++i) {
        v[i] = hp[tid + i * 128];
        s  += v[i];
        ss += v[i] * v[i];
    }
#pragma unroll
    for (int o = 16; o > 0; o >>= 1) {
        s  += __shfl_xor_sync(0xFFFFFFFFu, s,  o);
        ss += __shfl_xor_sync(0xFFFFFFFFu, ss, o);
    }
    __shared__ float sm[4], sm2[4];
    if ((tid & 31) == 0) { sm[tid >> 5] = s; sm2[tid >> 5] = ss; }
    __syncthreads();
    s  = sm[0]  + sm[1]  + sm[2]  + sm[3];
    ss = sm2[0] + sm2[1] + sm2[2] + sm2[3];

    const float mu   = s * (1.0f / HID);
    const float var  = ss * (1.0f / HID) - mu * mu;
    const float rstd = rsqrtf(var + 1e-6f);
#pragma unroll
    for (int i = 0; i < 4; ++i) {
        const int c = tid + i * 128;
        const float hn = (v[i] - mu) * rstd * gamma[c] + beta[c];
        const __nv_bfloat16 hi = __float2bfloat16(hn);
        g_hn_hi[row * HID + c] = hi;
        g_hn_lo[row * HID + c] = __float2bfloat16(hn - __bfloat162float(hi));
    }
}

// ---------------------------------------------------------------------------
// Kernel 3: z = hn @ w2 + b2 (split HMMA); epilogue: z out + zn hi/lo split
// tile 128x128 (full OUT), K=512 in 4 chunks
// ---------------------------------------------------------------------------
__global__ __launch_bounds__(256, 1) void gemm2_mma_kernel(
    const float* __restrict__ b2, float* __restrict__ z_out)
{
    extern __shared__ char smem[];
    const uint32_t sb = smem_u32(smem);
    const int tid = threadIdx.x;
    const int wid = tid >> 5;
    const int lane = tid & 31;
    const int wm = wid & 3, wn = wid >> 2;
    const int rb = blockIdx.x;

    const uint32_t lrow = (uint32_t)(lane & 15);
    const uint32_t lcol = (uint32_t)(lane >> 4) * 16;
    const uint32_t aoff = (uint32_t)(wm * 32) * ROWB + lrow * ROWB + lcol;
    const uint32_t boff = (uint32_t)(wn * 64) * ROWB + lrow * ROWB + lcol;

    float acc[2][8][4] = {};

    for (int kt = 0; kt < HID / 128; ++kt) {
        const int k0 = kt * 128;
        load_tile(g_hn_hi  + (rb * 128) * HID + k0, HID, smem + 0 * TILEB, tid);
        load_tile(g_hn_lo  + (rb * 128) * HID + k0, HID, smem + 1 * TILEB, tid);
        load_tile(g_w2t_hi + k0,                    HID, smem + 2 * TILEB, tid);
        load_tile(g_w2t_lo + k0,                    HID, smem + 3 * TILEB, tid);
        __syncthreads();
        mma_3split(sb + 0 * TILEB + aoff, sb + 1 * TILEB + aoff,
                   sb + 2 * TILEB + boff, sb + 3 * TILEB + boff, acc);
        __syncthreads();
    }

    float* Cs = (float*)smem;
    stage_acc(Cs, acc, wm, wn, lane);
    __syncthreads();

    if (tid < 128) {
        const int r = tid;
        const int grow = rb * 128 + r;
        float s = 0.f;
#pragma unroll 8
        for (int c = 0; c < 128; ++c) {
            const float v = Cs[r * 133 + c] + b2[c];
            Cs[r * 133 + c] = v;
            s += v * v;
        }
        const float inv = 1.0f / fmaxf(sqrtf(s), 1e-8f);
#pragma unroll 8
        for (int c = 0; c < 128; ++c) {
            const float v = Cs[r * 133 + c];
            z_out[grow * OUT + c] = v;
            const float zn = v * inv;
            const __nv_bfloat16 hi = __float2bfloat16(zn);
            g_zn_hi[grow * OUT + c] = hi;
            g_zn_lo[grow * OUT + c] = __float2bfloat16(zn - __bfloat162float(hi));
        }
    }
}

// ---------------------------------------------------------------------------
// Kernel 4: y_hat = zn @ zn^T (split HMMA), exact triangular linear grid
// ---------------------------------------------------------------------------
#define NT (B / 128)                    // 64 tile-blocks per dim
#define NTRI (NT * (NT + 1) / 2)        // 2080

__global__ __launch_bounds__(256, 1) void gram_mma_kernel(float* __restrict__ yhat)
{
    // decode triangular linear index -> (bi, bj), bj >= bi
    const int t = blockIdx.x;
    int bi = (int)((129.0 - sqrt((double)(129 * 129 - 8 * t))) * 0.5);
    while (64 * (bi + 1) - (bi + 1) * bi / 2 <= t) ++bi;
    while (64 * bi - bi * (bi - 1) / 2 > t) --bi;
    const int bj = bi + (t - (64 * bi - bi * (bi - 1) / 2));

    extern __shared__ char smem[];
    const uint32_t sb = smem_u32(smem);
    const int tid = threadIdx.x;
    const int wid = tid >> 5;
    const int lane = tid & 31;
    const int wm = wid & 3, wn = wid >> 2;

    load_tile(g_zn_hi + (bi * 128) * OUT, OUT, smem + 0 * TILEB, tid);
    load_tile(g_zn_lo + (bi * 128) * OUT, OUT, smem + 1 * TILEB, tid);
    load_tile(g_zn_hi + (bj * 128) * OUT, OUT, smem + 2 * TILEB, tid);
    load_tile(g_zn_lo + (bj * 128) * OUT, OUT, smem + 3 * TILEB, tid);
    __syncthreads();

    float acc[2][8][4] = {};

    const uint32_t lrow = (uint32_t)(lane & 15);
    const uint32_t lcol = (uint32_t)(lane >> 4) * 16;
    const uint32_t aoff = (uint32_t)(wm * 32) * ROWB + lrow * ROWB + lcol;
    const uint32_t boff = (uint32_t)(wn * 64) * ROWB + lrow * ROWB + lcol;

    mma_3split(sb + 0 * TILEB + aoff, sb + 1 * TILEB + aoff,
               sb + 2 * TILEB + boff, sb + 3 * TILEB + boff, acc);

    __syncthreads();
    float* Cs = (float*)smem;
    stage_acc(Cs, acc, wm, wn, lane);
    __syncthreads();

    const long rowD = (long)bi * 128;
    const long colD = (long)bj * 128;
#pragma unroll
    for (int it = 0; it < 64; ++it) {
        const int idx = tid + it * 256;
        const int r = idx >> 7, c = idx & 127;
        yhat[(rowD + r) * (long)B + colD + c] = Cs[r * 133 + c];
    }
    if (bi != bj) {
#pragma unroll
        for (int it = 0; it < 64; ++it) {
            const int idx = tid + it * 256;
            const int r = idx >> 7, c = idx & 127;
            yhat[(colD + r) * (long)B + rowD + c] = Cs[c * 133 + r];
        }
    }
}

// ---------------------------------------------------------------------------
extern "C" void kernel_launch(void* const* d_in, const int* in_sizes, int n_in,
                              void* d_out, int out_size)
{
    const float* x       = (const float*)d_in[0];
    const float* w1      = (const float*)d_in[1];
    const float* b1      = (const float*)d_in[2];
    const float* prelu_a = (const float*)d_in[3];
    const float* gamma   = (const float*)d_in[4];
    const float* beta    = (const float*)d_in[5];
    const float* w2      = (const float*)d_in[6];
    const float* b2      = (const float*)d_in[7];

    float* out   = (float*)d_out;
    float* z_out = out;                    // [8192, 128]
    float* yhat  = out + (size_t)B * OUT;  // [8192, 8192]

    cudaFuncSetAttribute(gemm1_mma_kernel, cudaFuncAttributeMaxDynamicSharedMemorySize, MMA_SMEM);
    cudaFuncSetAttribute(gemm2_mma_kernel, cudaFuncAttributeMaxDynamicSharedMemorySize, MMA_SMEM);
    cudaFuncSetAttribute(gram_mma_kernel,  cudaFuncAttributeMaxDynamicSharedMemorySize, MMA_SMEM);

    split_x_kernel<<<(B * IN_DIM / 2) / 256, 256>>>(x);
    split_w1t_kernel<<<(HID * IN_DIM) / 256, 256>>>(w1);
    split_w2t_kernel<<<(OUT * HID) / 256, 256>>>(w2);

    gemm1_mma_kernel<<<dim3(HID / 128, B / 128), 256, MMA_SMEM>>>(b1, prelu_a);
    ln_split_kernel<<<B, 128>>>(gamma, beta);
    gemm2_mma_kernel<<<B / 128, 256, MMA_SMEM>>>(b2, z_out);
    gram_mma_kernel<<<NTRI, 256, MMA_SMEM>>>(yhat);
}

// round 7
// speedup vs baseline: 2.1653x; 1.2017x over previous
#include <cuda_runtime.h>
#include <cuda_bf16.h>
#include <math.h>
#include <cstdint>

#define B      8192
#define IN_DIM 1024
#define HID    512
#define OUT    128

// scratch (device globals — no allocation allowed)
__device__ float g_h[B * HID];                                // 16 MB
__device__ __align__(256) __nv_bfloat16 g_x_hi[B * IN_DIM];   // 16 MB
__device__ __align__(256) __nv_bfloat16 g_x_lo[B * IN_DIM];   // 16 MB
__device__ __align__(256) __nv_bfloat16 g_w1t_hi[HID * IN_DIM]; // [n][k]
__device__ __align__(256) __nv_bfloat16 g_w1t_lo[HID * IN_DIM];
__device__ __align__(256) __nv_bfloat16 g_hn_hi[B * HID];     // 8 MB
__device__ __align__(256) __nv_bfloat16 g_hn_lo[B * HID];     // 8 MB
__device__ __align__(256) __nv_bfloat16 g_w2t_hi[OUT * HID];  // [n][k]
__device__ __align__(256) __nv_bfloat16 g_w2t_lo[OUT * HID];
__device__ __align__(256) __nv_bfloat16 g_zn_hi[B * OUT];     // 2 MB
__device__ __align__(256) __nv_bfloat16 g_zn_lo[B * OUT];     // 2 MB

__device__ __forceinline__ uint32_t smem_u32(const void* p) {
    uint32_t a;
    asm("{ .reg .u64 t; cvta.to.shared.u64 t, %1; cvt.u32.u64 %0, t; }"
        : "=r"(a) : "l"(p));
    return a;
}

#define LDSM_X4(r0, r1, r2, r3, addr) \
    asm volatile("ldmatrix.sync.aligned.m8n8.x4.shared.b16 {%0,%1,%2,%3}, [%4];" \
        : "=r"(r0), "=r"(r1), "=r"(r2), "=r"(r3) : "r"(addr))

#define MMA_BF16(d, a, b0, b1) \
    asm volatile("mma.sync.aligned.m16n8k16.row.col.f32.bf16.bf16.f32 " \
        "{%0,%1,%2,%3}, {%4,%5,%6,%7}, {%8,%9}, {%0,%1,%2,%3};" \
        : "+f"((d)[0]), "+f"((d)[1]), "+f"((d)[2]), "+f"((d)[3]) \
        : "r"((a)[0]), "r"((a)[1]), "r"((a)[2]), "r"((a)[3]), "r"(b0), "r"(b1))

#define CP16(dst, src) \
    asm volatile("cp.async.cg.shared.global [%0], [%1], 16;" \
        :: "r"(dst), "l"(src) : "memory")
#define CP_COMMIT() asm volatile("cp.async.commit_group;" ::: "memory")
#define CP_WAIT(n)  asm volatile("cp.async.wait_group %0;" :: "n"(n) : "memory")

// ---------------------------------------------------------------------------
// shared helpers
// ---------------------------------------------------------------------------
// 3-split HMMA over one K-chunk: (Ah,Bh)+(Ah,Bl)+(Al,Bh)
// RB = smem row stride bytes, NKS = k16 steps, NJ = n-frags (8 cols each)
template<int RB, int NKS, int NJ>
__device__ __forceinline__ void mma3(uint32_t aH, uint32_t aL,
                                     uint32_t bH, uint32_t bL, float* acc)
{
#pragma unroll
    for (int s = 0; s < 3; ++s) {
        const uint32_t aBase = (s == 2) ? aL : aH;
        const uint32_t bBase = (s == 1) ? bL : bH;
#pragma unroll
        for (int ks = 0; ks < NKS; ++ks) {
            const uint32_t kb = (uint32_t)ks * 32;
            uint32_t a[2][4];
            LDSM_X4(a[0][0], a[0][1], a[0][2], a[0][3], aBase + kb);
            LDSM_X4(a[1][0], a[1][1], a[1][2], a[1][3], aBase + 16 * RB + kb);
            uint32_t b[NJ][2];
#pragma unroll
            for (int p = 0; p < NJ / 2; ++p) {
                uint32_t r0, r1, r2, r3;
                LDSM_X4(r0, r1, r2, r3, bBase + (uint32_t)p * 16 * RB + kb);
                b[2 * p + 0][0] = r0; b[2 * p + 0][1] = r2;
                b[2 * p + 1][0] = r1; b[2 * p + 1][1] = r3;
            }
#pragma unroll
            for (int i = 0; i < 2; ++i)
#pragma unroll
                for (int j = 0; j < NJ; ++j)
                    MMA_BF16(&acc[(i * NJ + j) * 4], a[i], b[j][0], b[j][1]);
        }
    }
}

// stage acc fragments into Cs (stride 133 floats). warp col width = NJ*8
template<int NJ>
__device__ __forceinline__ void stage_acc(
    float* Cs, const float* acc, int wm, int wn, int lane)
{
#pragma unroll
    for (int i = 0; i < 2; ++i) {
        const int r0 = wm * 32 + i * 16 + (lane >> 2);
#pragma unroll
        for (int j = 0; j < NJ; ++j) {
            const int c0 = wn * (NJ * 8) + j * 8 + (lane & 3) * 2;
            const float* f = &acc[(i * NJ + j) * 4];
            Cs[r0 * 133 + c0]           = f[0];
            Cs[r0 * 133 + c0 + 1]       = f[1];
            Cs[(r0 + 8) * 133 + c0]     = f[2];
            Cs[(r0 + 8) * 133 + c0 + 1] = f[3];
        }
    }
}

// cp.async a 128-row x 256B tile into smem (RB=272)
__device__ __forceinline__ void cp_tile_128(
    const __nv_bfloat16* __restrict__ g, int gstride, uint32_t dst, int tid)
{
#pragma unroll
    for (int it = 0; it < 8; ++it) {
        const int idx = tid + it * 256;
        const int row = idx >> 4, c16 = idx & 15;
        CP16(dst + row * 272 + c16 * 16, g + row * gstride + c16 * 8);
    }
}
// cp.async a 64-row x 256B tile (RB=272)
__device__ __forceinline__ void cp_tile_64(
    const __nv_bfloat16* __restrict__ g, int gstride, uint32_t dst, int tid)
{
#pragma unroll
    for (int it = 0; it < 4; ++it) {
        const int idx = tid + it * 256;
        const int row = idx >> 4, c16 = idx & 15;
        CP16(dst + row * 272 + c16 * 16, g + row * gstride + c16 * 8);
    }
}
// cp.async a 128-row x 128B tile (RB=144, BK=64): 128 rows x 8 chunks = 1024
__device__ __forceinline__ void cp_tile_g1(
    const __nv_bfloat16* __restrict__ g, int gstride, uint32_t dst, int tid)
{
#pragma unroll
    for (int it = 0; it < 4; ++it) {
        const int idx = tid + it * 256;
        const int row = idx >> 3, c16 = idx & 7;
        CP16(dst + row * 144 + c16 * 16, g + row * gstride + c16 * 8);
    }
}

// ---------------------------------------------------------------------------
// Prologue kernels: split inputs to bf16 hi/lo (w transposed)
// ---------------------------------------------------------------------------
__global__ __launch_bounds__(256) void split_x_kernel(const float* __restrict__ x)
{
    const int idx = blockIdx.x * 256 + threadIdx.x;
    const float2 v = ((const float2*)x)[idx];
    const __nv_bfloat16 h0 = __float2bfloat16(v.x);
    const __nv_bfloat16 h1 = __float2bfloat16(v.y);
    g_x_hi[2 * idx]     = h0;
    g_x_hi[2 * idx + 1] = h1;
    g_x_lo[2 * idx]     = __float2bfloat16(v.x - __bfloat162float(h0));
    g_x_lo[2 * idx + 1] = __float2bfloat16(v.y - __bfloat162float(h1));
}

__global__ __launch_bounds__(256) void split_w1t_kernel(const float* __restrict__ w1)
{
    const int idx = blockIdx.x * 256 + threadIdx.x;
    const int n = idx >> 10, k = idx & 1023;
    const float v = w1[k * HID + n];
    const __nv_bfloat16 h = __float2bfloat16(v);
    g_w1t_hi[idx] = h;
    g_w1t_lo[idx] = __float2bfloat16(v - __bfloat162float(h));
}

__global__ __launch_bounds__(256) void split_w2t_kernel(const float* __restrict__ w2)
{
    const int idx = blockIdx.x * 256 + threadIdx.x;
    const int n = idx >> 9, k = idx & 511;
    const float v = w2[k * OUT + n];
    const __nv_bfloat16 h = __float2bfloat16(v);
    g_w2t_hi[idx] = h;
    g_w2t_lo[idx] = __float2bfloat16(v - __bfloat162float(h));
}

// ---------------------------------------------------------------------------
// Kernel 1: h = PReLU(x @ w1 + b1). tile 128x128, BK=64, 2-stage cp.async.
// ---------------------------------------------------------------------------
#define G1_TILE  (128 * 144)          // 18432
#define G1_STAGE (4 * G1_TILE)        // 73728: [xh, xl, wh, wl]
#define G1_SMEM  (2 * G1_STAGE)       // 147456

__global__ __launch_bounds__(256, 1) void gemm1_mma_kernel(
    const float* __restrict__ b1, const float* __restrict__ prelu_a)
{
    extern __shared__ char smem[];
    const uint32_t sb = smem_u32(smem);
    const int tid = threadIdx.x;
    const int wid = tid >> 5;
    const int lane = tid & 31;
    const int wm = wid & 3, wn = wid >> 2;
    const int rb = blockIdx.y, cb = blockIdx.x;

    const __nv_bfloat16* xh = g_x_hi   + (rb * 128) * IN_DIM;
    const __nv_bfloat16* xl = g_x_lo   + (rb * 128) * IN_DIM;
    const __nv_bfloat16* wh = g_w1t_hi + (cb * 128) * IN_DIM;
    const __nv_bfloat16* wl = g_w1t_lo + (cb * 128) * IN_DIM;

    // prologue: stage 0
    cp_tile_g1(xh, IN_DIM, sb + 0 * G1_TILE, tid);
    cp_tile_g1(xl, IN_DIM, sb + 1 * G1_TILE, tid);
    cp_tile_g1(wh, IN_DIM, sb + 2 * G1_TILE, tid);
    cp_tile_g1(wl, IN_DIM, sb + 3 * G1_TILE, tid);
    CP_COMMIT();

    const uint32_t lrow = (uint32_t)(lane & 15);
    const uint32_t lcol = (uint32_t)(lane >> 4) * 16;
    const uint32_t aoff = (uint32_t)(wm * 32) * 144 + lrow * 144 + lcol;
    const uint32_t boff = (uint32_t)(wn * 64) * 144 + lrow * 144 + lcol;

    float acc[2 * 8 * 4] = {};

    for (int kt = 0; kt < 16; ++kt) {
        if (kt < 15) {
            const int k0 = (kt + 1) * 64;
            const uint32_t st = sb + ((kt + 1) & 1) * G1_STAGE;
            cp_tile_g1(xh + k0, IN_DIM, st + 0 * G1_TILE, tid);
            cp_tile_g1(xl + k0, IN_DIM, st + 1 * G1_TILE, tid);
            cp_tile_g1(wh + k0, IN_DIM, st + 2 * G1_TILE, tid);
            cp_tile_g1(wl + k0, IN_DIM, st + 3 * G1_TILE, tid);
            CP_COMMIT();
            CP_WAIT(1);
        } else {
            CP_WAIT(0);
        }
        __syncthreads();
        const uint32_t st = sb + (kt & 1) * G1_STAGE;
        mma3<144, 4, 8>(st + 0 * G1_TILE + aoff, st + 1 * G1_TILE + aoff,
                        st + 2 * G1_TILE + boff, st + 3 * G1_TILE + boff, acc);
        __syncthreads();
    }

    // epilogue in stage 0 (last mma read stage 1)
    float* Cs = (float*)smem;
    stage_acc<8>(Cs, acc, wm, wn, lane);
    __syncthreads();

    const float alpha = prelu_a[0];
#pragma unroll
    for (int it = 0; it < 64; ++it) {
        const int idx = tid + it * 256;
        const int r = idx >> 7, c = idx & 127;
        float v = Cs[r * 133 + c] + b1[cb * 128 + c];
        v = (v >= 0.0f) ? v : alpha * v;
        g_h[(rb * 128 + r) * HID + cb * 128 + c] = v;
    }
}

// ---------------------------------------------------------------------------
// Kernel 2: LayerNorm rows of g_h -> hn split bf16 hi/lo
// ---------------------------------------------------------------------------
__global__ __launch_bounds__(128) void ln_split_kernel(
    const float* __restrict__ gamma, const float* __restrict__ beta)
{
    const int row = blockIdx.x;
    const float* hp = g_h + row * HID;
    const int tid = threadIdx.x;

    float v[4];
    float s = 0.f, ss = 0.f;
#pragma unroll
    for (int i = 0; i < 4; ++i) {
        v[i] = hp[tid + i * 128];
        s  += v[i];
        ss += v[i] * v[i];
    }
#pragma unroll
    for (int o = 16; o > 0; o >>= 1) {
        s  += __shfl_xor_sync(0xFFFFFFFFu, s,  o);
        ss += __shfl_xor_sync(0xFFFFFFFFu, ss, o);
    }
    __shared__ float sm[4], sm2[4];
    if ((tid & 31) == 0) { sm[tid >> 5] = s; sm2[tid >> 5] = ss; }
    __syncthreads();
    s  = sm[0]  + sm[1]  + sm[2]  + sm[3];
    ss = sm2[0] + sm2[1] + sm2[2] + sm2[3];

    const float mu   = s * (1.0f / HID);
    const float var  = ss * (1.0f / HID) - mu * mu;
    const float rstd = rsqrtf(var + 1e-6f);
#pragma unroll
    for (int i = 0; i < 4; ++i) {
        const int c = tid + i * 128;
        const float hn = (v[i] - mu) * rstd * gamma[c] + beta[c];
        const __nv_bfloat16 hi = __float2bfloat16(hn);
        g_hn_hi[row * HID + c] = hi;
        g_hn_lo[row * HID + c] = __float2bfloat16(hn - __bfloat162float(hi));
    }
}

// ---------------------------------------------------------------------------
// Kernel 3: z = hn @ w2 + b2; epilogue row-norm + zn split.
// tile 64x128, BK=128, 2-stage cp.async. grid = 128 CTAs.
// ---------------------------------------------------------------------------
#define G2_TA    (64 * 272)            // 17408 (A tile)
#define G2_TB    (128 * 272)           // 34816 (B tile)
#define G2_STAGE (2 * G2_TA + 2 * G2_TB)  // 104448: [Ah, Al, Bh, Bl]
#define G2_SMEM  (2 * G2_STAGE)        // 208896

__global__ __launch_bounds__(256, 1) void gemm2_mma_kernel(
    const float* __restrict__ b2, float* __restrict__ z_out)
{
    extern __shared__ char smem[];
    const uint32_t sb = smem_u32(smem);
    const int tid = threadIdx.x;
    const int wid = tid >> 5;
    const int lane = tid & 31;
    const int wm = wid & 1, wn = wid >> 1;   // 2x4 warps, warp tile 32x32
    const int rb = blockIdx.x;

    const __nv_bfloat16* ah = g_hn_hi + (rb * 64) * HID;
    const __nv_bfloat16* al = g_hn_lo + (rb * 64) * HID;

    cp_tile_64 (ah,       HID, sb + 0,                 tid);
    cp_tile_64 (al,       HID, sb + G2_TA,             tid);
    cp_tile_128(g_w2t_hi, HID, sb + 2 * G2_TA,         tid);
    cp_tile_128(g_w2t_lo, HID, sb + 2 * G2_TA + G2_TB, tid);
    CP_COMMIT();

    const uint32_t lrow = (uint32_t)(lane & 15);
    const uint32_t lcol = (uint32_t)(lane >> 4) * 16;
    const uint32_t aoff = (uint32_t)(wm * 32) * 272 + lrow * 272 + lcol;
    const uint32_t boff = (uint32_t)(wn * 32) * 272 + lrow * 272 + lcol;

    float acc[2 * 4 * 4] = {};

    for (int kt = 0; kt < 4; ++kt) {
        if (kt < 3) {
            const int k0 = (kt + 1) * 128;
            const uint32_t st = sb + ((kt + 1) & 1) * G2_STAGE;
            cp_tile_64 (ah + k0,       HID, st + 0,                 tid);
            cp_tile_64 (al + k0,       HID, st + G2_TA,             tid);
            cp_tile_128(g_w2t_hi + k0, HID, st + 2 * G2_TA,         tid);
            cp_tile_128(g_w2t_lo + k0, HID, st + 2 * G2_TA + G2_TB, tid);
            CP_COMMIT();
            CP_WAIT(1);
        } else {
            CP_WAIT(0);
        }
        __syncthreads();
        const uint32_t st = sb + (kt & 1) * G2_STAGE;
        mma3<272, 8, 4>(st + aoff, st + G2_TA + aoff,
                        st + 2 * G2_TA + boff, st + 2 * G2_TA + G2_TB + boff, acc);
        __syncthreads();
    }

    float* Cs = (float*)smem;   // 64 x 133 floats, stage 0 dead (last mma = stage 1)
    stage_acc<4>(Cs, acc, wm, wn, lane);
    __syncthreads();

    if (tid < 64) {
        const int r = tid;
        const int grow = rb * 64 + r;
        float s = 0.f;
#pragma unroll 8
        for (int c = 0; c < 128; ++c) {
            const float v = Cs[r * 133 + c] + b2[c];
            Cs[r * 133 + c] = v;
            s += v * v;
        }
        const float inv = 1.0f / fmaxf(sqrtf(s), 1e-8f);
#pragma unroll 8
        for (int c = 0; c < 128; ++c) {
            const float v = Cs[r * 133 + c];
            z_out[grow * OUT + c] = v;
            const float zn = v * inv;
            const __nv_bfloat16 hi = __float2bfloat16(zn);
            g_zn_hi[grow * OUT + c] = hi;
            g_zn_lo[grow * OUT + c] = __float2bfloat16(zn - __bfloat162float(hi));
        }
    }
}

// ---------------------------------------------------------------------------
// Kernel 4: y_hat = zn @ zn^T. Each CTA: one bi row-band, up to 4 j-tiles.
// A tiles resident; B tiles 2-stage cp.async; C staged in consumed B stage.
// ---------------------------------------------------------------------------
#define GR_TILE  (128 * 272)           // 34816
#define GR_A     (2 * GR_TILE)         // 69632: [Ah, Al]
#define GR_STAGE (2 * GR_TILE)         // 69632: [Bh, Bl]
#define GR_SMEM  (GR_A + 2 * GR_STAGE) // 208896
#define NT       (B / 128)             // 64
#define JPC      4

__global__ __launch_bounds__(256, 1) void gram_mma_kernel(float* __restrict__ yhat)
{
    // decode blockIdx.x -> (bi, chunk)
    int t = blockIdx.x;
    int bi = 0;
    for (; bi < NT; ++bi) {
        const int c = (NT - bi + JPC - 1) >> 2;
        if (t < c) break;
        t -= c;
    }
    const int j0 = bi + t * JPC;
    const int count = min(JPC, NT - j0);

    extern __shared__ char smem[];
    const uint32_t sb = smem_u32(smem);
    const int tid = threadIdx.x;
    const int wid = tid >> 5;
    const int lane = tid & 31;
    const int wm = wid & 3, wn = wid >> 2;

    // group 0: A tiles + B(j0); group 1: B(j0+1)
    cp_tile_128(g_zn_hi + (bi * 128) * OUT, OUT, sb + 0 * GR_TILE, tid);
    cp_tile_128(g_zn_lo + (bi * 128) * OUT, OUT, sb + 1 * GR_TILE, tid);
    cp_tile_128(g_zn_hi + (j0 * 128) * OUT, OUT, sb + GR_A + 0 * GR_TILE, tid);
    cp_tile_128(g_zn_lo + (j0 * 128) * OUT, OUT, sb + GR_A + 1 * GR_TILE, tid);
    CP_COMMIT();
    if (count > 1) {
        cp_tile_128(g_zn_hi + ((j0 + 1) * 128) * OUT, OUT,
                    sb + GR_A + GR_STAGE + 0 * GR_TILE, tid);
        cp_tile_128(g_zn_lo + ((j0 + 1) * 128) * OUT, OUT,
                    sb + GR_A + GR_STAGE + 1 * GR_TILE, tid);
        CP_COMMIT();
    }

    const uint32_t lrow = (uint32_t)(lane & 15);
    const uint32_t lcol = (uint32_t)(lane >> 4) * 16;
    const uint32_t aoff = (uint32_t)(wm * 32) * 272 + lrow * 272 + lcol;
    const uint32_t boff = (uint32_t)(wn * 64) * 272 + lrow * 272 + lcol;

    for (int jj = 0; jj < count; ++jj) {
        const int p = jj & 1;
        const int bj = j0 + jj;
        const uint32_t bst = sb + GR_A + p * GR_STAGE;

        if (jj + 1 < count) { CP_WAIT(1); } else { CP_WAIT(0); }
        __syncthreads();

        float acc[2 * 8 * 4] = {};
        mma3<272, 8, 8>(sb + aoff, sb + GR_TILE + aoff,
                        bst + boff, bst + GR_TILE + boff, acc);
        __syncthreads();

        float* Cs = (float*)(smem + GR_A + p * GR_STAGE);  // consumed B stage
        stage_acc<8>(Cs, acc, wm, wn, lane);
        __syncthreads();

        const long rowD = (long)bi * 128;
        const long colD = (long)bj * 128;
#pragma unroll
        for (int it = 0; it < 64; ++it) {
            const int idx = tid + it * 256;
            const int r = idx >> 7, c = idx & 127;
            yhat[(rowD + r) * (long)B + colD + c] = Cs[r * 133 + c];
        }
        if (bi != bj) {
#pragma unroll
            for (int it = 0; it < 64; ++it) {
                const int idx = tid + it * 256;
                const int r = idx >> 7, c = idx & 127;
                yhat[(colD + r) * (long)B + rowD + c] = Cs[c * 133 + r];
            }
        }
        __syncthreads();

        if (jj + 2 < count) {   // next-next B into stage p (now free)
            cp_tile_128(g_zn_hi + ((long)(j0 + jj + 2) * 128) * OUT, OUT,
                        sb + GR_A + p * GR_STAGE + 0 * GR_TILE, tid);
            cp_tile_128(g_zn_lo + ((long)(j0 + jj + 2) * 128) * OUT, OUT,
                        sb + GR_A + p * GR_STAGE + 1 * GR_TILE, tid);
            CP_COMMIT();
        }
    }
}

// grid size for gram: sum over bi of ceil((NT-bi)/JPC) = 544
#define GRAM_GRID 544

// ---------------------------------------------------------------------------
extern "C" void kernel_launch(void* const* d_in, const int* in_sizes, int n_in,
                              void* d_out, int out_size)
{
    const float* x       = (const float*)d_in[0];
    const float* w1      = (const float*)d_in[1];
    const float* b1      = (const float*)d_in[2];
    const float* prelu_a = (const float*)d_in[3];
    const float* gamma   = (const float*)d_in[4];
    const float* beta    = (const float*)d_in[5];
    const float* w2      = (const float*)d_in[6];
    const float* b2      = (const float*)d_in[7];

    float* out   = (float*)d_out;
    float* z_out = out;                    // [8192, 128]
    float* yhat  = out + (size_t)B * OUT;  // [8192, 8192]

    cudaFuncSetAttribute(gemm1_mma_kernel, cudaFuncAttributeMaxDynamicSharedMemorySize, G1_SMEM);
    cudaFuncSetAttribute(gemm2_mma_kernel, cudaFuncAttributeMaxDynamicSharedMemorySize, G2_SMEM);
    cudaFuncSetAttribute(gram_mma_kernel,  cudaFuncAttributeMaxDynamicSharedMemorySize, GR_SMEM);

    split_x_kernel<<<(B * IN_DIM / 2) / 256, 256>>>(x);
    split_w1t_kernel<<<(HID * IN_DIM) / 256, 256>>>(w1);
    split_w2t_kernel<<<(OUT * HID) / 256, 256>>>(w2);

    gemm1_mma_kernel<<<dim3(HID / 128, B / 128), 256, G1_SMEM>>>(b1, prelu_a);
    ln_split_kernel<<<B, 128>>>(gamma, beta);
    gemm2_mma_kernel<<<B / 64, 256, G2_SMEM>>>(b2, z_out);
    gram_mma_kernel<<<GRAM_GRID, 256, GR_SMEM>>>(yhat);
}